// round 1
// baseline (speedup 1.0000x reference)
#include <cuda_runtime.h>

#define N_NODES 2048
#define N_EDGES 16384
#define B_DIM 8
#define C_DIM 64
#define T_DIM 12
#define BT 96                 // B*T
#define OUT_DIM 64

// ---------------- scratch (static __device__, no allocation) ----------------
__device__ float g_h2[N_NODES * BT * C_DIM];     // h * log2(e), [n][bt][c]
__device__ float g_feats[N_NODES * BT * C_DIM];  // h + agg,     [n][bt][c]
__device__ float g_e2[N_EDGES * C_DIM];          // edge_feat * log2(e)
__device__ int   g_cnt[N_NODES];
__device__ int   g_rowptr[N_NODES + 1];
__device__ int   g_cursor[N_NODES];
__device__ int   g_eidx[N_EDGES];
__device__ int   g_esrc[N_EDGES];

// ---------------- stage A: transpose [B,C,T,N] -> [N,BT,C], pre-scale by log2e
__global__ void k_transpose(const float* __restrict__ nf) {
    __shared__ float tile[32][33];
    const float LOG2E = 1.4426950408889634f;
    int bt = blockIdx.z;
    int b = bt / T_DIM, t = bt - b * T_DIM;
    int c0 = blockIdx.y << 5, n0 = blockIdx.x << 5;
    int tx = threadIdx.x, ty = threadIdx.y;
#pragma unroll
    for (int i = 0; i < 4; i++) {
        int c = c0 + ty + i * 8;
        tile[ty + i * 8][tx] =
            nf[(((b * C_DIM + c) * T_DIM + t) * N_NODES) + n0 + tx] * LOG2E;
    }
    __syncthreads();
#pragma unroll
    for (int i = 0; i < 4; i++) {
        int n = n0 + ty + i * 8;
        g_h2[((n * BT + bt) << 6) + c0 + tx] = tile[tx][ty + i * 8];
    }
}

__global__ void k_escale(const float* __restrict__ ef) {
    int i = blockIdx.x * blockDim.x + threadIdx.x;
    g_e2[i] = ef[i] * 1.4426950408889634f;
}

// ---------------- CSR build ----------------
__global__ void k_zero() {
    int i = blockIdx.x * blockDim.x + threadIdx.x;
    if (i < N_NODES) g_cnt[i] = 0;
}

__global__ void k_hist(const int* __restrict__ dst) {
    int e = blockIdx.x * blockDim.x + threadIdx.x;
    if (e < N_EDGES) atomicAdd(&g_cnt[dst[e]], 1);
}

// single-block Hillis-Steele inclusive scan over 2048 counts
__global__ void k_scan() {
    __shared__ int sh[2048];
    int t = threadIdx.x;
    sh[t] = g_cnt[t];
    sh[t + 1024] = g_cnt[t + 1024];
    __syncthreads();
    for (int off = 1; off < 2048; off <<= 1) {
        int v0 = (t >= off) ? sh[t - off] : 0;
        int v1 = sh[t + 1024 - off];
        __syncthreads();
        sh[t] += v0;
        sh[t + 1024] += v1;
        __syncthreads();
    }
    g_rowptr[t + 1] = sh[t];
    g_rowptr[t + 1025] = sh[t + 1024];
    g_cursor[t] = (t == 0) ? 0 : sh[t - 1];
    g_cursor[t + 1024] = sh[t + 1023];
    if (t == 0) g_rowptr[0] = 0;
}

__global__ void k_scatter(const int* __restrict__ src, const int* __restrict__ dst) {
    int e = blockIdx.x * blockDim.x + threadIdx.x;
    if (e < N_EDGES) {
        int p = atomicAdd(&g_cursor[dst[e]], 1);
        g_eidx[p] = e;
        g_esrc[p] = src[e];
    }
}

// ---------------- stage B: per-destination message + softmax + agg + residual
// block = 1 dst node, 512 threads: c = tid&63, g = tid>>6 (8 groups),
// each thread owns 12 bt slots (bt = g*12 + j), state = (den, num) per slot.
// No max-tracking needed: r = relu(...)*log2e in [0, ~16], 2^r cannot overflow.
__global__ __launch_bounds__(512) void k_msg() {
    int n = blockIdx.x;
    int tid = threadIdx.x;
    int c = tid & 63, g = tid >> 6;
    int beg = g_rowptr[n], end = g_rowptr[n + 1];

    float den[12], num[12];
#pragma unroll
    for (int j = 0; j < 12; j++) { den[j] = 0.f; num[j] = 0.f; }

    int go = g * (12 * C_DIM) + c;  // g*768 + c

    for (int k = beg; k < end; k++) {
        int eid = __ldg(&g_eidx[k]);
        int s = __ldg(&g_esrc[k]);
        float ev = g_e2[(eid << 6) + c];
        const float* hp = g_h2 + s * (BT * C_DIM) + go;
#pragma unroll
        for (int j = 0; j < 12; j++) {
            float v = hp[j * 64] + ev;          // (h+e)*log2e
            float r = fmaxf(v, 0.f);            // relu (ALU pipe)
            float p;
            asm("ex2.approx.f32 %0, %1;" : "=f"(p) : "f"(r));  // exp(relu(h+e))
            den[j] += p;
            num[j] = fmaf(r, p, num[j]);
        }
    }

    const float LN2 = 0.6931471805599453f;
    const float* hq = g_h2 + n * (BT * C_DIM) + go;
    float* fq = g_feats + n * (BT * C_DIM) + go;
    bool has = (end > beg);
#pragma unroll
    for (int j = 0; j < 12; j++) {
        float agg = 0.f;
        if (has) {
            float rd;
            asm("rcp.approx.f32 %0, %1;" : "=f"(rd) : "f"(den[j]));
            // agg = ln2 * (num/den) + eps   (eps re-added once, exact vs ref)
            agg = fmaf(num[j] * rd, LN2, 1e-7f);
        }
        fq[j * 64] = fmaf(hq[j * 64], LN2, agg);  // feats = h + agg
    }
}

// ---------------- stage C: feats @ W + b, output transposed to [B,O,T,N]
union F2U { float2 f; unsigned long long u; };
__device__ __forceinline__ float2 ffma2(float2 a, float2 b, float2 c) {
    F2U A, Bu, Cu, D;
    A.f = a; Bu.f = b; Cu.f = c;
    asm("fma.rn.f32x2 %0, %1, %2, %3;" : "=l"(D.u) : "l"(A.u), "l"(Bu.u), "l"(Cu.u));
    return D.f;
}

__global__ __launch_bounds__(128) void k_gemm(const float* __restrict__ W,
                                              const float* __restrict__ bias,
                                              float* __restrict__ out) {
    __shared__ __align__(16) float sW[64 * 65];   // padded staging, conflict-free transpose
    __shared__ __align__(16) float sWT[64 * 64];  // W^T: [o][c]
    __shared__ float sB[64];
    int tid = threadIdx.x;
    int bt = blockIdx.y;
    int n = (blockIdx.x << 7) + tid;

    // coalesced load of W into padded smem
    for (int i = tid; i < 4096; i += 128) {
        int cc = i >> 6, o = i & 63;
        sW[cc * 65 + o] = W[i];
    }
    if (tid < 64) sB[tid] = bias[tid];
    __syncthreads();
    // smem->smem transpose (stride-65 read = bank-conflict-free)
    for (int i = tid; i < 4096; i += 128) {
        int o = i >> 6, cc = i & 63;
        sWT[i] = sW[cc * 65 + o];
    }
    __syncthreads();

    // load this thread's feats row (64 fp32) into registers as 32 float2
    float2 f[32];
    const float4* fp = (const float4*)(g_feats + (n * BT + bt) * 64);
#pragma unroll
    for (int q = 0; q < 16; q++) {
        float4 x = fp[q];
        f[2 * q] = make_float2(x.x, x.y);
        f[2 * q + 1] = make_float2(x.z, x.w);
    }

    int b = bt / T_DIM, t = bt - b * T_DIM;
    float* op = out + ((b * OUT_DIM) * T_DIM + t) * N_NODES + n;
    const float4* wp4 = (const float4*)sWT;
#pragma unroll 4
    for (int o = 0; o < 64; o++) {
        float2 a0 = make_float2(0.f, 0.f), a1 = make_float2(0.f, 0.f);
#pragma unroll
        for (int q = 0; q < 16; q++) {
            float4 w = wp4[(o << 4) + q];  // uniform broadcast LDS.128
            a0 = ffma2(f[2 * q], make_float2(w.x, w.y), a0);
            a1 = ffma2(f[2 * q + 1], make_float2(w.z, w.w), a1);
        }
        op[o * (T_DIM * N_NODES)] = a0.x + a0.y + a1.x + a1.y + sB[o];
    }
}

// ---------------- launch ----------------
extern "C" void kernel_launch(void* const* d_in, const int* in_sizes, int n_in,
                              void* d_out, int out_size) {
    const float* nf  = (const float*)d_in[0];  // node_feats [B,C,T,N]
    const float* ef  = (const float*)d_in[1];  // edge_feat  [E,1,1,C]
    const int*   src = (const int*)d_in[2];
    const int*   dst = (const int*)d_in[3];
    const float* W   = (const float*)d_in[4];
    const float* bvec= (const float*)d_in[5];
    float* out = (float*)d_out;

    k_transpose<<<dim3(N_NODES / 32, C_DIM / 32, BT), dim3(32, 8)>>>(nf);
    k_escale<<<(N_EDGES * C_DIM) / 256, 256>>>(ef);
    k_zero<<<N_NODES / 256, 256>>>();
    k_hist<<<N_EDGES / 256, 256>>>(dst);
    k_scan<<<1, 1024>>>();
    k_scatter<<<N_EDGES / 256, 256>>>(src, dst);
    k_msg<<<N_NODES, 512>>>();
    k_gemm<<<dim3(N_NODES / 128, BT), 128>>>(W, bvec, out);
}

// round 2
// speedup vs baseline: 1.1419x; 1.1419x over previous
#include <cuda_runtime.h>

#define N_NODES 2048
#define N_EDGES 16384
#define B_DIM 8
#define C_DIM 64
#define T_DIM 12
#define BT 96                 // B*T
#define OUT_DIM 64

// ---------------- scratch (static __device__, no allocation) ----------------
__device__ float g_h2[N_NODES * BT * C_DIM];     // h * log2(e), [n][bt][c]
__device__ float g_feats[N_NODES * BT * C_DIM];  // h + agg,     [n][bt][c]
__device__ float g_WT[64 * 64];                  // W^T [o][c]
__device__ int   g_cnt[N_NODES];
__device__ int   g_epack[N_NODES * 64];          // (eid<<11)|src per dst slot

// ---------------- packed f32x2 helpers ----------------
union F2U { float2 f; unsigned long long u; };
__device__ __forceinline__ float2 f2add(float2 a, float2 b) {
    F2U A, B2, D; A.f = a; B2.f = b;
    asm("add.rn.f32x2 %0, %1, %2;" : "=l"(D.u) : "l"(A.u), "l"(B2.u));
    return D.f;
}
__device__ __forceinline__ float2 f2fma(float2 a, float2 b, float2 c) {
    F2U A, B2, C2, D; A.f = a; B2.f = b; C2.f = c;
    asm("fma.rn.f32x2 %0, %1, %2, %3;" : "=l"(D.u) : "l"(A.u), "l"(B2.u), "l"(C2.u));
    return D.f;
}

// ---------------- stage 0: zero counters + transpose W (one tiny kernel) ----
__global__ void k_prep(const float* __restrict__ W) {
    int i = blockIdx.x * blockDim.x + threadIdx.x;
    if (i < 4096) {
        int o = i >> 6, c = i & 63;
        g_WT[i] = W[c * 64 + o];
    } else if (i < 4096 + N_NODES) {
        g_cnt[i - 4096] = 0;
    }
}

// ---------------- stage 0b: bucket-place edges per destination -------------
__global__ void k_build(const int* __restrict__ src, const int* __restrict__ dst) {
    int e = blockIdx.x * blockDim.x + threadIdx.x;
    int d = dst[e];
    int p = atomicAdd(&g_cnt[d], 1);
    g_epack[(d << 6) + p] = (e << 11) | src[e];
}

// ---------------- stage A: transpose [B,C,T,N] -> [N,BT,C], pre-scale log2e -
__global__ void k_transpose(const float* __restrict__ nf) {
    __shared__ float tile[32][33];
    const float LOG2E = 1.4426950408889634f;
    int bt = blockIdx.z;
    int b = bt / T_DIM, t = bt - b * T_DIM;
    int c0 = blockIdx.y << 5, n0 = blockIdx.x << 5;
    int tx = threadIdx.x, ty = threadIdx.y;
#pragma unroll
    for (int i = 0; i < 4; i++) {
        int c = c0 + ty + i * 8;
        tile[ty + i * 8][tx] =
            nf[(((b * C_DIM + c) * T_DIM + t) * N_NODES) + n0 + tx] * LOG2E;
    }
    __syncthreads();
#pragma unroll
    for (int i = 0; i < 4; i++) {
        int n = n0 + ty + i * 8;
        g_h2[((n * BT + bt) << 6) + c0 + tx] = tile[tx][ty + i * 8];
    }
}

// ---------------- stage B: message + softmax + agg + residual ---------------
// block = 1 dst node, 512 threads: cp = tid&31 (c-pair), grp = tid>>5 (16),
// each thread owns 6 bt slots (bt = grp*6 + j). Packed f32x2 math.
// No max-pass needed: r = relu(.)*log2e in [0,~16], 2^r cannot overflow.
__global__ __launch_bounds__(512) void k_msg(const float* __restrict__ ef) {
    __shared__ int s_ep[64];
    __shared__ int s_cnt;
    int n = blockIdx.x;
    int tid = threadIdx.x;
    if (tid == 0) s_cnt = g_cnt[n];
    if (tid < 64) s_ep[tid] = g_epack[(n << 6) + tid];
    __syncthreads();

    int cp = tid & 31;   // c-pair index (c = 2*cp, 2*cp+1)
    int grp = tid >> 5;  // 0..15
    int cnt = s_cnt;

    float2 den[6], num[6];
#pragma unroll
    for (int j = 0; j < 6; j++) {
        den[j] = make_float2(0.f, 0.f);
        num[j] = make_float2(0.f, 0.f);
    }

    const float LOG2E = 1.4426950408889634f;

    for (int k = 0; k < cnt; k++) {
        int pk = s_ep[k];
        int s = pk & 2047;
        int e = pk >> 11;
        float2 ev = *(const float2*)(ef + (e << 6) + (cp << 1));
        ev.x *= LOG2E; ev.y *= LOG2E;
        const float2* hp = (const float2*)(g_h2 + (s * BT + grp * 6) * 64) + cp;
#pragma unroll
        for (int j = 0; j < 6; j++) {
            float2 h = hp[j * 32];
            float2 v = f2add(h, ev);                      // (h+e)*log2e (packed)
            float rx = fmaxf(v.x, 0.f), ry = fmaxf(v.y, 0.f);
            float px, py;
            asm("ex2.approx.f32 %0, %1;" : "=f"(px) : "f"(rx));
            asm("ex2.approx.f32 %0, %1;" : "=f"(py) : "f"(ry));
            float2 p = make_float2(px, py);
            den[j] = f2add(den[j], p);
            num[j] = f2fma(make_float2(rx, ry), p, num[j]);
        }
    }

    const float LN2 = 0.6931471805599453f;
    const float2* hq = (const float2*)(g_h2 + (n * BT + grp * 6) * 64) + cp;
    float2* fq = (float2*)(g_feats + (n * BT + grp * 6) * 64) + cp;
    bool has = (cnt > 0);
#pragma unroll
    for (int j = 0; j < 6; j++) {
        float2 agg = make_float2(0.f, 0.f);
        if (has) {
            float dx, dy;
            asm("rcp.approx.f32 %0, %1;" : "=f"(dx) : "f"(den[j].x));
            asm("rcp.approx.f32 %0, %1;" : "=f"(dy) : "f"(den[j].y));
            agg.x = fmaf(num[j].x * dx, LN2, 1e-7f);
            agg.y = fmaf(num[j].y * dy, LN2, 1e-7f);
        }
        float2 h = hq[j * 32];
        float2 o;
        o.x = fmaf(h.x, LN2, agg.x);   // feats = h + agg   (h = h2*ln2)
        o.y = fmaf(h.y, LN2, agg.y);
        fq[j * 32] = o;
    }
}

// ---------------- stage C: feats @ W + b, output [B,O,T,N] ------------------
__global__ __launch_bounds__(128) void k_gemm(const float* __restrict__ bias,
                                              float* __restrict__ out) {
    __shared__ __align__(16) float sWT[64 * 64];  // W^T: [o][c]
    __shared__ float sB[64];
    int tid = threadIdx.x;
    int bt = blockIdx.y;
    int n = (blockIdx.x << 7) + tid;

    for (int i = tid; i < 4096; i += 128) sWT[i] = g_WT[i];   // coalesced
    if (tid < 64) sB[tid] = bias[tid];
    __syncthreads();

    // this thread's feats row (64 fp32) as 32 float2
    float2 f[32];
    const float4* fp = (const float4*)(g_feats + (n * BT + bt) * 64);
#pragma unroll
    for (int q = 0; q < 16; q++) {
        float4 x = fp[q];
        f[2 * q] = make_float2(x.x, x.y);
        f[2 * q + 1] = make_float2(x.z, x.w);
    }

    int b = bt / T_DIM, t = bt - b * T_DIM;
    float* op = out + ((b * OUT_DIM) * T_DIM + t) * N_NODES + n;
    const float4* wp4 = (const float4*)sWT;
#pragma unroll 4
    for (int o = 0; o < 64; o++) {
        float2 a0 = make_float2(0.f, 0.f), a1 = make_float2(0.f, 0.f);
#pragma unroll
        for (int q = 0; q < 16; q++) {
            float4 w = wp4[(o << 4) + q];  // uniform broadcast LDS.128
            a0 = f2fma(f[2 * q], make_float2(w.x, w.y), a0);
            a1 = f2fma(f[2 * q + 1], make_float2(w.z, w.w), a1);
        }
        op[o * (T_DIM * N_NODES)] = a0.x + a0.y + a1.x + a1.y + sB[o];
    }
}

// ---------------- launch ----------------
extern "C" void kernel_launch(void* const* d_in, const int* in_sizes, int n_in,
                              void* d_out, int out_size) {
    const float* nf   = (const float*)d_in[0];  // node_feats [B,C,T,N]
    const float* ef   = (const float*)d_in[1];  // edge_feat  [E,1,1,C]
    const int*   src  = (const int*)d_in[2];
    const int*   dst  = (const int*)d_in[3];
    const float* W    = (const float*)d_in[4];
    const float* bvec = (const float*)d_in[5];
    float* out = (float*)d_out;

    k_prep<<<24, 256>>>(W);                                   // WT + zero cnt
    k_build<<<N_EDGES / 256, 256>>>(src, dst);                // bucket edges
    k_transpose<<<dim3(N_NODES / 32, C_DIM / 32, BT), dim3(32, 8)>>>(nf);
    k_msg<<<N_NODES, 512>>>(ef);
    k_gemm<<<dim3(N_NODES / 128, BT), 128>>>(bvec, out);
}

// round 3
// speedup vs baseline: 1.2073x; 1.0573x over previous
#include <cuda_runtime.h>

#define N_NODES 2048
#define N_EDGES 16384
#define B_DIM 8
#define C_DIM 64
#define T_DIM 12
#define BT 96                 // B*T
#define OUT_DIM 64

// ---------------- scratch (static __device__, no allocation) ----------------
__device__ float g_h2[N_NODES * BT * C_DIM];     // h * log2(e), [n][bt][c]
__device__ float g_feats[N_NODES * BT * C_DIM];  // h + agg,     [n][bt][c]
__device__ float g_WT[64 * 64];                  // W^T [o][c]
__device__ int   g_cnt[N_NODES];
__device__ int   g_epack[N_NODES * 64];          // (eid<<11)|src per dst slot

// ---------------- packed f32x2 helpers ----------------
union F2U { float2 f; unsigned long long u; };
__device__ __forceinline__ float2 f2add(float2 a, float2 b) {
    F2U A, B2, D; A.f = a; B2.f = b;
    asm("add.rn.f32x2 %0, %1, %2;" : "=l"(D.u) : "l"(A.u), "l"(B2.u));
    return D.f;
}
__device__ __forceinline__ float2 f2fma(float2 a, float2 b, float2 c) {
    F2U A, B2, C2, D; A.f = a; B2.f = b; C2.f = c;
    asm("fma.rn.f32x2 %0, %1, %2, %3;" : "=l"(D.u) : "l"(A.u), "l"(B2.u), "l"(C2.u));
    return D.f;
}
__device__ __forceinline__ float4 f4add(float4 a, float4 b) {
    float2 lo = f2add(make_float2(a.x, a.y), make_float2(b.x, b.y));
    float2 hi = f2add(make_float2(a.z, a.w), make_float2(b.z, b.w));
    return make_float4(lo.x, lo.y, hi.x, hi.y);
}
__device__ __forceinline__ float ex2f(float x) {
    float r; asm("ex2.approx.f32 %0, %1;" : "=f"(r) : "f"(x)); return r;
}
__device__ __forceinline__ float rcpf(float x) {
    float r; asm("rcp.approx.f32 %0, %1;" : "=f"(r) : "f"(x)); return r;
}

// ---------------- stage A: transpose [B,C,T,N] -> [N,BT,C] (*log2e),
//                  plus (extra z-slice) W transpose + counter zeroing --------
__global__ void k_transpose(const float* __restrict__ nf,
                            const float* __restrict__ W) {
    if (blockIdx.z == BT) {
        if (blockIdx.x == 0 && blockIdx.y == 0) {
            int t = threadIdx.y * 32 + threadIdx.x;
            for (int i = t; i < 4096; i += 256)
                g_WT[i] = W[(i & 63) * 64 + (i >> 6)];   // WT[o][c] = W[c][o]
            for (int i = t; i < N_NODES; i += 256) g_cnt[i] = 0;
        }
        return;
    }
    __shared__ float tile[32][33];
    const float LOG2E = 1.4426950408889634f;
    int bt = blockIdx.z;
    int b = bt / T_DIM, t = bt - b * T_DIM;
    int c0 = blockIdx.y << 5, n0 = blockIdx.x << 5;
    int tx = threadIdx.x, ty = threadIdx.y;
#pragma unroll
    for (int i = 0; i < 4; i++) {
        int c = c0 + ty + i * 8;
        tile[ty + i * 8][tx] =
            nf[(((b * C_DIM + c) * T_DIM + t) * N_NODES) + n0 + tx] * LOG2E;
    }
    __syncthreads();
#pragma unroll
    for (int i = 0; i < 4; i++) {
        int n = n0 + ty + i * 8;
        g_h2[((n * BT + bt) << 6) + c0 + tx] = tile[tx][ty + i * 8];
    }
}

// ---------------- stage 0b: bucket-place edges per destination -------------
__global__ void k_build(const int* __restrict__ src, const int* __restrict__ dst) {
    int e = blockIdx.x * blockDim.x + threadIdx.x;
    int d = dst[e];
    int p = atomicAdd(&g_cnt[d], 1);
    g_epack[(d << 6) + p] = (e << 11) | src[e];
}

// ---------------- stage B: message + softmax + agg + residual ---------------
// grid (N_NODES, 3), block 256: cq = tid&15 (c-quad), grp = tid>>4 (16 groups),
// each thread owns 2 bt slots. Edge features staged in smem once per block.
// Edge loop processes 2 edges/iter -> 6 independent LDG.128 in flight.
// No max-pass needed: r = relu(.)*log2e in [0,~16], 2^r cannot overflow.
#define BT_PER_BLK 32
__global__ __launch_bounds__(256, 4) void k_msg(const float* __restrict__ ef) {
    __shared__ __align__(16) float s_ev[64 * 64];
    __shared__ int s_ep[64];
    __shared__ int s_cnt;
    int n = blockIdx.x;
    int tid = threadIdx.x;
    if (tid == 0) s_cnt = g_cnt[n];
    if (tid < 64) s_ep[tid] = g_epack[(n << 6) + tid];
    __syncthreads();
    int cnt = s_cnt;
    const float LOG2E = 1.4426950408889634f;
    for (int i = tid; i < (cnt << 6); i += 256) {
        int eid = s_ep[i >> 6] >> 11;
        s_ev[i] = ef[(eid << 6) + (i & 63)] * LOG2E;   // coalesced stage
    }
    __syncthreads();

    int cq = tid & 15;     // c-quad: c = 4*cq .. 4*cq+3
    int grp = tid >> 4;    // 0..15
    int bt0 = blockIdx.y * BT_PER_BLK + grp * 2;

    float4 den0 = make_float4(0, 0, 0, 0), den1 = den0;
    float4 num0 = den0, num1 = den0;

    const float4* evp = (const float4*)s_ev;   // [edge][16 quads]

#define PROC(Hq, Eq, DEN, NUM)                                            \
    {                                                                     \
        float4 v = f4add(Hq, Eq);                                         \
        float4 r = make_float4(fmaxf(v.x, 0.f), fmaxf(v.y, 0.f),          \
                               fmaxf(v.z, 0.f), fmaxf(v.w, 0.f));         \
        float4 p = make_float4(ex2f(r.x), ex2f(r.y), ex2f(r.z), ex2f(r.w)); \
        DEN = f4add(DEN, p);                                              \
        float2 nlo = f2fma(make_float2(r.x, r.y), make_float2(p.x, p.y),  \
                           make_float2(NUM.x, NUM.y));                    \
        float2 nhi = f2fma(make_float2(r.z, r.w), make_float2(p.z, p.w),  \
                           make_float2(NUM.z, NUM.w));                    \
        NUM = make_float4(nlo.x, nlo.y, nhi.x, nhi.y);                    \
    }

    int k = 0;
    for (; k + 2 <= cnt; k += 2) {
        int s0 = s_ep[k] & 2047;
        int s1 = s_ep[k + 1] & 2047;
        const float4* h0 = (const float4*)(g_h2 + (s0 * BT + bt0) * 64) + cq;
        const float4* h1 = (const float4*)(g_h2 + (s1 * BT + bt0) * 64) + cq;
        float4 a0 = h0[0], a1 = h0[16];     // bt0, bt0+1 of edge0
        float4 b0 = h1[0], b1 = h1[16];     // bt0, bt0+1 of edge1
        float4 e0 = evp[(k << 4) + cq];
        float4 e1 = evp[((k + 1) << 4) + cq];
        PROC(a0, e0, den0, num0);
        PROC(a1, e0, den1, num1);
        PROC(b0, e1, den0, num0);
        PROC(b1, e1, den1, num1);
    }
    if (k < cnt) {
        int s0 = s_ep[k] & 2047;
        const float4* h0 = (const float4*)(g_h2 + (s0 * BT + bt0) * 64) + cq;
        float4 a0 = h0[0], a1 = h0[16];
        float4 e0 = evp[(k << 4) + cq];
        PROC(a0, e0, den0, num0);
        PROC(a1, e0, den1, num1);
    }
#undef PROC

    const float LN2 = 0.6931471805599453f;
    const float EPS = 1e-7f;
    const float4* hq = (const float4*)(g_h2 + (n * BT + bt0) * 64) + cq;
    float4* fq = (float4*)(g_feats + (n * BT + bt0) * 64) + cq;
    bool has = (cnt > 0);
#pragma unroll
    for (int j = 0; j < 2; j++) {
        float4 den = j ? den1 : den0;
        float4 num = j ? num1 : num0;
        float4 h = hq[j * 16];
        float4 agg = make_float4(0, 0, 0, 0);
        if (has) {
            agg.x = fmaf(num.x * rcpf(den.x), LN2, EPS);
            agg.y = fmaf(num.y * rcpf(den.y), LN2, EPS);
            agg.z = fmaf(num.z * rcpf(den.z), LN2, EPS);
            agg.w = fmaf(num.w * rcpf(den.w), LN2, EPS);
        }
        float4 o;
        o.x = fmaf(h.x, LN2, agg.x);
        o.y = fmaf(h.y, LN2, agg.y);
        o.z = fmaf(h.z, LN2, agg.z);
        o.w = fmaf(h.w, LN2, agg.w);
        fq[j * 16] = o;
    }
}

// ---------------- stage C: feats @ W + b, output [B,O,T,N] ------------------
__global__ __launch_bounds__(128) void k_gemm(const float* __restrict__ bias,
                                              float* __restrict__ out) {
    __shared__ __align__(16) float sWT[64 * 64];  // W^T: [o][c]
    __shared__ float sB[64];
    int tid = threadIdx.x;
    int bt = blockIdx.y;
    int n = (blockIdx.x << 7) + tid;

    for (int i = tid; i < 4096; i += 128) sWT[i] = g_WT[i];   // coalesced
    if (tid < 64) sB[tid] = bias[tid];
    __syncthreads();

    // this thread's feats row (64 fp32) as 32 float2
    float2 f[32];
    const float4* fp = (const float4*)(g_feats + (n * BT + bt) * 64);
#pragma unroll
    for (int q = 0; q < 16; q++) {
        float4 x = fp[q];
        f[2 * q] = make_float2(x.x, x.y);
        f[2 * q + 1] = make_float2(x.z, x.w);
    }

    int b = bt / T_DIM, t = bt - b * T_DIM;
    float* op = out + ((b * OUT_DIM) * T_DIM + t) * N_NODES + n;
    const float4* wp4 = (const float4*)sWT;
#pragma unroll 4
    for (int o = 0; o < 64; o++) {
        float2 a0 = make_float2(0.f, 0.f), a1 = make_float2(0.f, 0.f);
#pragma unroll
        for (int q = 0; q < 16; q++) {
            float4 w = wp4[(o << 4) + q];  // uniform broadcast LDS.128
            a0 = f2fma(f[2 * q], make_float2(w.x, w.y), a0);
            a1 = f2fma(f[2 * q + 1], make_float2(w.z, w.w), a1);
        }
        op[o * (T_DIM * N_NODES)] = a0.x + a0.y + a1.x + a1.y + sB[o];
    }
}

// ---------------- launch ----------------
extern "C" void kernel_launch(void* const* d_in, const int* in_sizes, int n_in,
                              void* d_out, int out_size) {
    const float* nf   = (const float*)d_in[0];  // node_feats [B,C,T,N]
    const float* ef   = (const float*)d_in[1];  // edge_feat  [E,1,1,C]
    const int*   src  = (const int*)d_in[2];
    const int*   dst  = (const int*)d_in[3];
    const float* W    = (const float*)d_in[4];
    const float* bvec = (const float*)d_in[5];
    float* out = (float*)d_out;

    k_transpose<<<dim3(N_NODES / 32, C_DIM / 32, BT + 1), dim3(32, 8)>>>(nf, W);
    k_build<<<N_EDGES / 256, 256>>>(src, dst);
    k_msg<<<dim3(N_NODES, 3), 256>>>(ef);
    k_gemm<<<dim3(N_NODES / 128, BT), 128>>>(bvec, out);
}

// round 4
// speedup vs baseline: 1.5380x; 1.2739x over previous
#include <cuda_runtime.h>

#define N_NODES 2048
#define N_EDGES 16384
#define B_DIM 8
#define C_DIM 64
#define T_DIM 12
#define BT 96                 // B*T
#define OUT_DIM 64

// ---------------- scratch (static __device__, no allocation) ----------------
__device__ float g_h2[N_NODES * BT * C_DIM];     // h * log2(e), [n][bt][c]
__device__ float g_feats[BT * N_NODES * C_DIM];  // h + agg,     [bt][n][c]
__device__ int   g_cnt[N_NODES];
__device__ int   g_epack[N_NODES * 64];          // (eid<<11)|src per dst slot

// ---------------- packed f32x2 helpers ----------------
union F2U { float2 f; unsigned long long u; };
__device__ __forceinline__ float2 f2add(float2 a, float2 b) {
    F2U A, B2, D; A.f = a; B2.f = b;
    asm("add.rn.f32x2 %0, %1, %2;" : "=l"(D.u) : "l"(A.u), "l"(B2.u));
    return D.f;
}
__device__ __forceinline__ float2 f2fma(float2 a, float2 b, float2 c) {
    F2U A, B2, C2, D; A.f = a; B2.f = b; C2.f = c;
    asm("fma.rn.f32x2 %0, %1, %2, %3;" : "=l"(D.u) : "l"(A.u), "l"(B2.u), "l"(C2.u));
    return D.f;
}
__device__ __forceinline__ float4 f4add(float4 a, float4 b) {
    float2 lo = f2add(make_float2(a.x, a.y), make_float2(b.x, b.y));
    float2 hi = f2add(make_float2(a.z, a.w), make_float2(b.z, b.w));
    return make_float4(lo.x, lo.y, hi.x, hi.y);
}
__device__ __forceinline__ float ex2f(float x) {
    float r; asm("ex2.approx.f32 %0, %1;" : "=f"(r) : "f"(x)); return r;
}
__device__ __forceinline__ float rcpf(float x) {
    float r; asm("rcp.approx.f32 %0, %1;" : "=f"(r) : "f"(x)); return r;
}

// ---------------- stage A: transpose [B,C,T,N] -> [N,BT,C] (*log2e),
//                  plus (extra z-slice) counter zeroing ----------------------
__global__ void k_transpose(const float* __restrict__ nf) {
    if (blockIdx.z == BT) {
        if (blockIdx.x == 0 && blockIdx.y == 0) {
            int t = threadIdx.y * 32 + threadIdx.x;
            for (int i = t; i < N_NODES; i += 256) g_cnt[i] = 0;
        }
        return;
    }
    __shared__ float tile[32][33];
    const float LOG2E = 1.4426950408889634f;
    int bt = blockIdx.z;
    int b = bt / T_DIM, t = bt - b * T_DIM;
    int c0 = blockIdx.y << 5, n0 = blockIdx.x << 5;
    int tx = threadIdx.x, ty = threadIdx.y;
#pragma unroll
    for (int i = 0; i < 4; i++) {
        int c = c0 + ty + i * 8;
        tile[ty + i * 8][tx] =
            nf[(((b * C_DIM + c) * T_DIM + t) * N_NODES) + n0 + tx] * LOG2E;
    }
    __syncthreads();
#pragma unroll
    for (int i = 0; i < 4; i++) {
        int n = n0 + ty + i * 8;
        g_h2[((n * BT + bt) << 6) + c0 + tx] = tile[tx][ty + i * 8];
    }
}

// ---------------- stage 0b: bucket-place edges per destination -------------
__global__ void k_build(const int* __restrict__ src, const int* __restrict__ dst) {
    int e = blockIdx.x * blockDim.x + threadIdx.x;
    int d = dst[e];
    int p = atomicAdd(&g_cnt[d], 1);
    g_epack[(d << 6) + p] = (e << 11) | src[e];
}

// ---------------- stage B: message + softmax + agg + residual ---------------
// grid (N_NODES, 3), block 256: cq = tid&15 (c-quad), grp = tid>>4 (16 groups),
// each thread owns 2 bt slots. Edge features staged in smem once per block.
// No max-pass needed: r = relu(.)*log2e in [0,~16], 2^r cannot overflow.
#define BT_PER_BLK 32
__global__ __launch_bounds__(256, 4) void k_msg(const float* __restrict__ ef) {
    __shared__ __align__(16) float s_ev[64 * 64];
    __shared__ int s_ep[64];
    __shared__ int s_cnt;
    int n = blockIdx.x;
    int tid = threadIdx.x;
    if (tid == 0) s_cnt = g_cnt[n];
    if (tid < 64) s_ep[tid] = g_epack[(n << 6) + tid];
    __syncthreads();
    int cnt = s_cnt;
    const float LOG2E = 1.4426950408889634f;
    for (int i = tid; i < (cnt << 6); i += 256) {
        int eid = s_ep[i >> 6] >> 11;
        s_ev[i] = ef[(eid << 6) + (i & 63)] * LOG2E;   // coalesced stage
    }
    __syncthreads();

    int cq = tid & 15;     // c-quad: c = 4*cq .. 4*cq+3
    int grp = tid >> 4;    // 0..15
    int bt0 = blockIdx.y * BT_PER_BLK + grp * 2;

    float4 den0 = make_float4(0, 0, 0, 0), den1 = den0;
    float4 num0 = den0, num1 = den0;

    const float4* evp = (const float4*)s_ev;   // [edge][16 quads]

#define PROC(Hq, Eq, DEN, NUM)                                            \
    {                                                                     \
        float4 v = f4add(Hq, Eq);                                         \
        float4 r = make_float4(fmaxf(v.x, 0.f), fmaxf(v.y, 0.f),          \
                               fmaxf(v.z, 0.f), fmaxf(v.w, 0.f));         \
        float4 p = make_float4(ex2f(r.x), ex2f(r.y), ex2f(r.z), ex2f(r.w)); \
        DEN = f4add(DEN, p);                                              \
        float2 nlo = f2fma(make_float2(r.x, r.y), make_float2(p.x, p.y),  \
                           make_float2(NUM.x, NUM.y));                    \
        float2 nhi = f2fma(make_float2(r.z, r.w), make_float2(p.z, p.w),  \
                           make_float2(NUM.z, NUM.w));                    \
        NUM = make_float4(nlo.x, nlo.y, nhi.x, nhi.y);                    \
    }

    int k = 0;
    for (; k + 2 <= cnt; k += 2) {
        int s0 = s_ep[k] & 2047;
        int s1 = s_ep[k + 1] & 2047;
        const float4* h0 = (const float4*)(g_h2 + (s0 * BT + bt0) * 64) + cq;
        const float4* h1 = (const float4*)(g_h2 + (s1 * BT + bt0) * 64) + cq;
        float4 a0 = h0[0], a1 = h0[16];     // bt0, bt0+1 of edge0
        float4 b0 = h1[0], b1 = h1[16];     // bt0, bt0+1 of edge1
        float4 e0 = evp[(k << 4) + cq];
        float4 e1 = evp[((k + 1) << 4) + cq];
        PROC(a0, e0, den0, num0);
        PROC(a1, e0, den1, num1);
        PROC(b0, e1, den0, num0);
        PROC(b1, e1, den1, num1);
    }
    if (k < cnt) {
        int s0 = s_ep[k] & 2047;
        const float4* h0 = (const float4*)(g_h2 + (s0 * BT + bt0) * 64) + cq;
        float4 a0 = h0[0], a1 = h0[16];
        float4 e0 = evp[(k << 4) + cq];
        PROC(a0, e0, den0, num0);
        PROC(a1, e0, den1, num1);
    }
#undef PROC

    const float LN2 = 0.6931471805599453f;
    const float EPS = 1e-7f;
    const float4* hq = (const float4*)(g_h2 + (n * BT + bt0) * 64) + cq;
    bool has = (cnt > 0);
#pragma unroll
    for (int j = 0; j < 2; j++) {
        float4 den = j ? den1 : den0;
        float4 num = j ? num1 : num0;
        float4 h = hq[j * 16];
        float4 agg = make_float4(0, 0, 0, 0);
        if (has) {
            agg.x = fmaf(num.x * rcpf(den.x), LN2, EPS);
            agg.y = fmaf(num.y * rcpf(den.y), LN2, EPS);
            agg.z = fmaf(num.z * rcpf(den.z), LN2, EPS);
            agg.w = fmaf(num.w * rcpf(den.w), LN2, EPS);
        }
        float4 o;
        o.x = fmaf(h.x, LN2, agg.x);
        o.y = fmaf(h.y, LN2, agg.y);
        o.z = fmaf(h.z, LN2, agg.z);
        o.w = fmaf(h.w, LN2, agg.w);
        // feats layout [bt][n][c]
        float4* fq = (float4*)(g_feats + (((bt0 + j) * N_NODES + n) << 6)) + cq;
        *fq = o;
    }
}

// ---------------- stage C: register-tiled GEMM, out [B,O,T,N] ---------------
// grid (16 n-blocks, 96 bt), block 256. Thread tile: 4n x 8o.
// tx = tid&31 (n-quad), ty = tid>>5 (o-octet). smem: sA[c][n] 32KB + sW 16KB.
__global__ __launch_bounds__(256) void k_gemm(const float* __restrict__ W,
                                              const float* __restrict__ bias,
                                              float* __restrict__ out) {
    __shared__ float sA[64][128];                 // [c][n] 32KB
    __shared__ __align__(16) float sW[64 * 64];   // [c][o] 16KB (same as W)
    __shared__ float sB[64];
    int tid = threadIdx.x;
    int bt = blockIdx.y;
    int n0 = blockIdx.x << 7;

    // W: direct coalesced copy (already [c][o], o contiguous)
    {
        const float4* Wv = (const float4*)W;
        float4* sWv = (float4*)sW;
        for (int i = tid; i < 1024; i += 256) sWv[i] = Wv[i];
        if (tid < 64) sB[tid] = bias[tid];
    }
    // feats tile: contiguous 32KB at g_feats[bt][n0..n0+127][.], transpose to sA[c][n]
    {
        int r = tid & 127;            // n row (lanes -> distinct rows, conflict-free STS)
        int qs = (tid >> 7) * 8;      // quad start (0 or 8)
        const float4* fp = (const float4*)(g_feats + ((bt * N_NODES + n0 + r) << 6)) + qs;
#pragma unroll
        for (int q = 0; q < 8; q++) {
            float4 v = fp[q];
            int c = (qs + q) << 2;
            sA[c][r] = v.x; sA[c + 1][r] = v.y; sA[c + 2][r] = v.z; sA[c + 3][r] = v.w;
        }
    }
    __syncthreads();

    int tx = tid & 31;   // n-quad: n = n0 + tx*4 ..+3
    int ty = tid >> 5;   // o-octet: o = ty*8 .. ty*8+7

    float2 acc[4][4];
#pragma unroll
    for (int i = 0; i < 4; i++)
#pragma unroll
        for (int p = 0; p < 4; p++) acc[i][p] = make_float2(0.f, 0.f);

    const float4* sWv4 = (const float4*)sW;
#pragma unroll 8
    for (int c = 0; c < 64; c++) {
        float4 a4 = *(const float4*)&sA[c][tx << 2];
        float4 w0 = sWv4[(c << 4) + (ty << 1)];       // uniform per warp
        float4 w1 = sWv4[(c << 4) + (ty << 1) + 1];
        float2 wp[4] = {{w0.x, w0.y}, {w0.z, w0.w}, {w1.x, w1.y}, {w1.z, w1.w}};
        float av[4] = {a4.x, a4.y, a4.z, a4.w};
#pragma unroll
        for (int i = 0; i < 4; i++) {
            float2 ad = make_float2(av[i], av[i]);
#pragma unroll
            for (int p = 0; p < 4; p++) acc[i][p] = f2fma(ad, wp[p], acc[i][p]);
        }
    }

    // epilogue: +bias, store STG.128 over n per output o
    int b = bt / T_DIM, t = bt - b * T_DIM;
    float* obase = out + ((b * OUT_DIM) * T_DIM + t) * N_NODES + n0 + (tx << 2);
#pragma unroll
    for (int p = 0; p < 4; p++) {
        int oe = (ty << 3) + (p << 1);
        float2 bb = *(const float2*)&sB[oe];
        float4 ve, vo;
        ve.x = acc[0][p].x + bb.x; vo.x = acc[0][p].y + bb.y;
        ve.y = acc[1][p].x + bb.x; vo.y = acc[1][p].y + bb.y;
        ve.z = acc[2][p].x + bb.x; vo.z = acc[2][p].y + bb.y;
        ve.w = acc[3][p].x + bb.x; vo.w = acc[3][p].y + bb.y;
        *(float4*)(obase + (long long)oe * (T_DIM * N_NODES)) = ve;
        *(float4*)(obase + (long long)(oe + 1) * (T_DIM * N_NODES)) = vo;
    }
}

// ---------------- launch ----------------
extern "C" void kernel_launch(void* const* d_in, const int* in_sizes, int n_in,
                              void* d_out, int out_size) {
    const float* nf   = (const float*)d_in[0];  // node_feats [B,C,T,N]
    const float* ef   = (const float*)d_in[1];  // edge_feat  [E,1,1,C]
    const int*   src  = (const int*)d_in[2];
    const int*   dst  = (const int*)d_in[3];
    const float* W    = (const float*)d_in[4];
    const float* bvec = (const float*)d_in[5];
    float* out = (float*)d_out;

    k_transpose<<<dim3(N_NODES / 32, C_DIM / 32, BT + 1), dim3(32, 8)>>>(nf);
    k_build<<<N_EDGES / 256, 256>>>(src, dst);
    k_msg<<<dim3(N_NODES, 3), 256>>>(ef);
    k_gemm<<<dim3(N_NODES / 128, BT), 256>>>(W, bvec, out);
}